// round 8
// baseline (speedup 1.0000x reference)
#include <cuda_runtime.h>
#include <cuda_bf16.h>
#include <stdint.h>

// GCNProtein: 6-layer GCN, 1M nodes, 16M edges, dims 1->3->3->3->3->3->1.
// Round 8: edge passes are bound by random L2 op count (~3.9us/M ops, locked
// model). Reds (dst random) are irreducible; gathers are not: sort edges by
// SRC once (hist+scan+cursor scatter), then warp-consecutive edges share src
// (avg out-degree 16) and the per-instruction coalescer collapses 32 gather
// lanes to ~2-3 sectors. dst stays random -> reds stay spread (avoids the
// R3 dst-sorted line-hot atomic failure). 32M -> ~17.5M ops/pass.

#define NMAX 1000000
#define EMAX 16000000
#define SCAN_ITEMS 16
#define SCAN_THREADS 256
#define SCAN_BLOCK_ELEMS (SCAN_ITEMS * SCAN_THREADS)   // 4096
#define MAX_SCAN_BLOCKS 256                            // ceil(1e6/4096)=245

__device__ float4 g_x3[NMAX];    // 3-wide messages (padded to float4), layers 2-5
__device__ float4 g_agg3[NMAX];  // 3-wide accumulators (w stays 0)
__device__ float  g_x1[NMAX];    // scalar messages, layers 1 and 6
__device__ float  g_agg1[NMAX];  // scalar accumulator
__device__ int    g_cnt[NMAX];   // out-degree counts (by src)
__device__ int    g_off[NMAX];   // scan partials
__device__ int    g_cursor[NMAX];
__device__ int2   g_es[EMAX];    // (src,dst) pairs grouped by src
__device__ int    g_bsum[MAX_SCAN_BLOCKS];
__device__ int    g_bsum2[MAX_SCAN_BLOCKS];

__device__ __forceinline__ void red_add_f32(float* p, float v) {
    asm volatile("red.global.add.f32 [%0], %1;" :: "l"(p), "f"(v) : "memory");
}
__device__ __forceinline__ void red_add_v4_f32(float4* p, float4 v) {
    asm volatile("red.global.add.v4.f32 [%0], {%1, %2, %3, %4};"
                 :: "l"(p), "f"(v.x), "f"(v.y), "f"(v.z), "f"(v.w) : "memory");
}

// ---------------- build phase (group edges by src) ----------------

__global__ void k_init(const float* __restrict__ feat, const float* __restrict__ norm, int n) {
    int i = blockIdx.x * blockDim.x + threadIdx.x;
    if (i < n) {
        g_x1[i] = feat[i] * norm[i];
        g_agg1[i] = 0.f;
        g_agg3[i] = make_float4(0.f, 0.f, 0.f, 0.f);
        g_cnt[i] = 0;
    }
}

__global__ void k_hist(const int* __restrict__ src, int E) {
    int e = blockIdx.x * blockDim.x + threadIdx.x;
    if (e < E) atomicAdd(&g_cnt[src[e]], 1);
}

__global__ void k_scanA(int n) {
    int tid = threadIdx.x;
    int base = blockIdx.x * SCAN_BLOCK_ELEMS + tid * SCAN_ITEMS;
    int loc[SCAN_ITEMS];
    int s = 0;
#pragma unroll
    for (int k = 0; k < SCAN_ITEMS; k++) {
        int idx = base + k;
        int v = (idx < n) ? g_cnt[idx] : 0;
        loc[k] = s; s += v;
    }
    int lane = tid & 31, wid = tid >> 5;
    int x = s;
#pragma unroll
    for (int o = 1; o < 32; o <<= 1) {
        int y = __shfl_up_sync(0xFFFFFFFFu, x, o);
        if (lane >= o) x += y;
    }
    __shared__ int wsum[8];
    if (lane == 31) wsum[wid] = x;
    __syncthreads();
    int woff = 0;
    for (int w = 0; w < wid; w++) woff += wsum[w];
    int excl = woff + x - s;
#pragma unroll
    for (int k = 0; k < SCAN_ITEMS; k++) {
        int idx = base + k;
        if (idx < n) g_off[idx] = excl + loc[k];
    }
    if (tid == SCAN_THREADS - 1) g_bsum[blockIdx.x] = woff + x;
}

__global__ void k_scanB(int nb) {
    int tid = threadIdx.x;
    int v = (tid < nb) ? g_bsum[tid] : 0;
    int lane = tid & 31, wid = tid >> 5;
    int x = v;
#pragma unroll
    for (int o = 1; o < 32; o <<= 1) {
        int y = __shfl_up_sync(0xFFFFFFFFu, x, o);
        if (lane >= o) x += y;
    }
    __shared__ int wsum[8];
    if (lane == 31) wsum[wid] = x;
    __syncthreads();
    int woff = 0;
    for (int w = 0; w < wid; w++) woff += wsum[w];
    if (tid < nb) g_bsum2[tid] = woff + x - v;
}

__global__ void k_scanC(int n) {
    int i = blockIdx.x * blockDim.x + threadIdx.x;
    if (i < n) g_cursor[i] = g_off[i] + g_bsum2[i / SCAN_BLOCK_ELEMS];
}

__global__ void k_scatter(const int* __restrict__ src, const int* __restrict__ dst, int E) {
    int e = blockIdx.x * blockDim.x + threadIdx.x;
    if (e >= E) return;
    int s = src[e];
    int pos = atomicAdd(&g_cursor[s], 1);
    g_es[pos] = make_int2(s, dst[e]);
}

// ---------------- node kernels ----------------

__global__ void k_node_1to3(const float* __restrict__ norm,
                            const float* __restrict__ W, const float* __restrict__ b, int n) {
    int i = blockIdx.x * blockDim.x + threadIdx.x;
    if (i >= n) return;
    float nm = norm[i];
    float t = g_agg1[i] * nm;
    g_agg1[i] = 0.f;                     // ready for layer 6
    float h0 = fmaxf(fmaf(t, W[0], b[0]), 0.f);
    float h1 = fmaxf(fmaf(t, W[1], b[1]), 0.f);
    float h2 = fmaxf(fmaf(t, W[2], b[2]), 0.f);
    g_x3[i] = make_float4(h0 * nm, h1 * nm, h2 * nm, 0.f);
}

__global__ void k_node_3to3(const float* __restrict__ norm,
                            const float* __restrict__ W, const float* __restrict__ b, int n) {
    int i = blockIdx.x * blockDim.x + threadIdx.x;
    if (i >= n) return;
    float nm = norm[i];
    float4 a = g_agg3[i];
    g_agg3[i] = make_float4(0.f, 0.f, 0.f, 0.f);
    float a0 = a.x * nm, a1 = a.y * nm, a2 = a.z * nm;
    float h0 = fmaxf(fmaf(a0, W[0], fmaf(a1, W[3], fmaf(a2, W[6], b[0]))), 0.f);
    float h1 = fmaxf(fmaf(a0, W[1], fmaf(a1, W[4], fmaf(a2, W[7], b[1]))), 0.f);
    float h2 = fmaxf(fmaf(a0, W[2], fmaf(a1, W[5], fmaf(a2, W[8], b[2]))), 0.f);
    g_x3[i] = make_float4(h0 * nm, h1 * nm, h2 * nm, 0.f);
}

__global__ void k_node_3to_scalar(const float* __restrict__ norm,
                                  const float* __restrict__ W5, const float* __restrict__ b5,
                                  const float* __restrict__ W6, int n) {
    int i = blockIdx.x * blockDim.x + threadIdx.x;
    if (i >= n) return;
    float nm = norm[i];
    float4 a = g_agg3[i];
    float a0 = a.x * nm, a1 = a.y * nm, a2 = a.z * nm;
    float h0 = fmaxf(fmaf(a0, W5[0], fmaf(a1, W5[3], fmaf(a2, W5[6], b5[0]))), 0.f);
    float h1 = fmaxf(fmaf(a0, W5[1], fmaf(a1, W5[4], fmaf(a2, W5[7], b5[1]))), 0.f);
    float h2 = fmaxf(fmaf(a0, W5[2], fmaf(a1, W5[5], fmaf(a2, W5[8], b5[2]))), 0.f);
    g_x1[i] = nm * (h0 * W6[0] + h1 * W6[1] + h2 * W6[2]);
}

__global__ void k_node_final(const float* __restrict__ norm,
                             const float* __restrict__ b6,
                             float* __restrict__ out, int n) {
    int i = blockIdx.x * blockDim.x + threadIdx.x;
    if (i >= n) return;
    out[i] = fmaxf(fmaf(norm[i], g_agg1[i], b6[0]), 0.f);
}

// ---------------- edge kernels (src-sorted, 1 edge/thread) ----------------

// scalar: agg1[dst] += x1[src]; warp lanes share src -> gather broadcasts
__global__ void k_edge_s(int E) {
    int e = blockIdx.x * blockDim.x + threadIdx.x;
    if (e >= E) return;
    int2 p = g_es[e];
    float v = g_x1[p.x];
    red_add_f32(&g_agg1[p.y], v);
}

// 3-wide: agg3[dst] += x3[src], one v4 red per edge
__global__ void k_edge_v(int E) {
    int e = blockIdx.x * blockDim.x + threadIdx.x;
    if (e >= E) return;
    int2 p = g_es[e];
    float4 v = g_x3[p.x];
    red_add_v4_f32(&g_agg3[p.y], v);
}

// ---------------- launch ----------------

extern "C" void kernel_launch(void* const* d_in, const int* in_sizes, int n_in,
                              void* d_out, int out_size) {
    const int* big_i[2] = {nullptr, nullptr};
    const float* big_f[2] = {nullptr, nullptr};
    const float* small[12] = {nullptr};
    int ni = 0, nf = 0, ns = 0;
    int N = 0, E = 0;
    for (int i = 0; i < n_in; i++) {
        int sz = in_sizes[i];
        if (sz >= 10000000) {
            if (ni < 2) { big_i[ni++] = (const int*)d_in[i]; E = sz; }
        } else if (sz >= 100000) {
            if (nf < 2) { big_f[nf++] = (const float*)d_in[i]; N = sz; }
        } else {
            if (ns < 12) small[ns++] = (const float*)d_in[i];
        }
    }
    const float* feat = big_f[0];
    const float* norm = big_f[1];
    const int* src = big_i[0];
    const int* dst = big_i[1];
    const float *W1 = small[0], *b1 = small[1];
    const float *W2 = small[2], *b2 = small[3];
    const float *W3 = small[4], *b3 = small[5];
    const float *W4 = small[6], *b4 = small[7];
    const float *W5 = small[8], *b5 = small[9];
    const float *W6 = small[10], *b6 = small[11];
    float* out = (float*)d_out;

    const int TB = 256;
    int gn = (N + TB - 1) / TB;
    int ge = (E + TB - 1) / TB;
    int nscan = (N + SCAN_BLOCK_ELEMS - 1) / SCAN_BLOCK_ELEMS;

    // build: group edges by src (order within a group irrelevant)
    k_init<<<gn, TB>>>(feat, norm, N);
    k_hist<<<ge, TB>>>(src, E);
    k_scanA<<<nscan, SCAN_THREADS>>>(N);
    k_scanB<<<1, SCAN_THREADS>>>(nscan);
    k_scanC<<<gn, TB>>>(N);
    k_scatter<<<ge, TB>>>(src, dst, E);

    // 6 layers on src-sorted edges
    k_edge_s<<<ge, TB>>>(E);
    k_node_1to3<<<gn, TB>>>(norm, W1, b1, N);
    k_edge_v<<<ge, TB>>>(E);
    k_node_3to3<<<gn, TB>>>(norm, W2, b2, N);
    k_edge_v<<<ge, TB>>>(E);
    k_node_3to3<<<gn, TB>>>(norm, W3, b3, N);
    k_edge_v<<<ge, TB>>>(E);
    k_node_3to3<<<gn, TB>>>(norm, W4, b4, N);
    k_edge_v<<<ge, TB>>>(E);
    k_node_3to_scalar<<<gn, TB>>>(norm, W5, b5, W6, N);
    k_edge_s<<<ge, TB>>>(E);
    k_node_final<<<gn, TB>>>(norm, b6, out, N);
}